// round 4
// baseline (speedup 1.0000x reference)
#include <cuda_runtime.h>
#include <math.h>

// ---------------------------------------------------------------------------
// PlaneElement fused, rolling-window streaming version (spill-free under a
// 32-register clamp). Each interior thread owns 8 consecutive elements,
// processed left-to-right with a 3-wide A window and one carried flux.
// Edge blocks (2) use the guarded smem path. Grid finale via atomic ticket.
// Output: [outflow_q, infil_rate_element, infil_depth_element, max_cfl]
// ---------------------------------------------------------------------------

#define BLOCK 256
#define EPT   8
#define TILE  (BLOCK * EPT)      // 2048
#define MAX_BLOCKS 8192
#define EPSF  1e-8f

struct Consts {
    float raindt;      // rain_rate * dt
    float Ka, Kb;      // fp*dt = Ka + Kb*depth
    float WID, rcpWID;
    float css;         // sqrt(1+SS1^2)+sqrt(1+SS2^2)
    float l2cman;      // log2(sqrt(SL)/MAN)
    float dtdx;        // dt/dx
    float inv_dt;
};

__device__ float        g_psum[MAX_BLOCKS];
__device__ float        g_pmax[MAX_BLOCKS];
__device__ float        g_outflow;
__device__ unsigned int g_count = 0;

__device__ __forceinline__ float fast_lg2(float x)
{ float r; asm("lg2.approx.f32 %0, %1;" : "=f"(r) : "f"(x)); return r; }
__device__ __forceinline__ float fast_ex2(float x)
{ float r; asm("ex2.approx.f32 %0, %1;" : "=f"(r) : "f"(x)); return r; }

// p' = (max(A,EPS)/wp)^(2/3) * cman    (cman folded via log2)
// manning q = A * p'
__device__ __forceinline__ float manning_pc(float A, const Consts& c)
{
    float h      = A * c.rcpWID;
    float wp     = fmaf(h, c.css, c.WID);
    float A_safe = fmaxf(A, EPSF);
    float r      = __fdividef(A_safe, wp);
    float e      = fmaf(0.66666667f, fast_lg2(r), c.l2cman);
    return fast_ex2(e);
}

// Green-Ampt + rain: returns A, writes infil
__device__ __forceinline__ float ga_A(float d, const Consts& c, float& infil)
{
    float fpdt  = fmaf(c.Kb, d, c.Ka);
    float avail = c.raindt + d;
    infil       = fminf(fpdt, avail);
    return fmaxf(avail - infil, 0.0f) * c.WID;
}

// outgoing flux of the node with window (Am, A0, Ap) = A[j-1], A[j], A[j+1]
__device__ __forceinline__ float face_flux(float Am, float A0, float Ap, const Consts& c)
{
    float a = A0 - Am;
    float b = Ap - A0;
    float m = (fabsf(a) < fabsf(b)) ? a : b;
    float s = (a * b > 0.0f) ? m : 0.0f;
    float Af = fmaf(0.5f, s, A0);
    return Af * manning_pc(Af, c);
}

__global__ void __launch_bounds__(BLOCK, 4)
fused_kernel(const float* __restrict__ depth, int N, int nblocks,
             float* __restrict__ out,
             const float* rain_rate, const float* dt,
             const float* theta_current, const float* F_cumulative,
             const float* WID, const float* SS1, const float* SS2,
             const float* MAN, const float* SL, const float* dx,
             const float* Ks, const float* psi, const float* theta_s)
{
    __shared__ float sA[TILE + 8];   // edge path only
    __shared__ float sF[TILE + 1];   // edge path only
    __shared__ Consts sc;
    __shared__ float wsum[BLOCK / 32];
    __shared__ float wmax[BLOCK / 32];
    __shared__ int   s_last;

    const int tid  = threadIdx.x;
    const int base = blockIdx.x * TILE;

    if (tid == 0) {
        float rr  = *rain_rate,  dtv = *dt,  th = *theta_current, F = *F_cumulative;
        float wid = *WID, ss1 = *SS1, ss2 = *SS2, man = *MAN, sl = *SL, dxv = *dx;
        float ks  = *Ks,  ps  = *psi, ths = *theta_s;
        Consts c;
        c.raindt = rr * dtv;
        float dtheta = fmaxf(ths - th, 0.0f);
        float F_safe = fmaxf(F, 1e-6f);
        float ksdt   = ks * dtv;
        c.Kb = ksdt / F_safe;
        c.Ka = ksdt + c.Kb * (ps * dtheta);
        c.WID = wid;
        c.rcpWID = 1.0f / wid;
        c.css  = sqrtf(1.0f + ss1 * ss1) + sqrtf(1.0f + ss2 * ss2);
        c.l2cman = log2f(sqrtf(sl) / man);
        c.dtdx = dtv / dxv;
        c.inv_dt = 1.0f / dtv;
        sc = c;
    }
    __syncthreads();
    const Consts c = sc;

    const bool interior = (base - 2 >= 0) && (base + TILE + 8 <= N);

    float local_sum = 0.0f;
    float local_max = 0.0f;

    if (interior) {
        // ------------- rolling-window register path -------------
        const int t0 = base + tid * EPT;

        float4 q0 = *(const float4*)(depth + t0);
        float4 q1 = *(const float4*)(depth + t0 + 4);
        float dm2 = __ldg(depth + t0 - 2);
        float dm1 = __ldg(depth + t0 - 1);
        float dp8 = __ldg(depth + t0 + EPT);

        float junk;
        float Ajm1 = ga_A(dm2, c, junk);              // A[t0-2]
        float Aj   = ga_A(dm1, c, junk);              // A[t0-1]
        float Ajp1;                                    // A[t0]
        {
            float inf;
            Ajp1 = ga_A(q0.x, c, inf);
            local_sum += inf;
        }
        float flux_prev = face_flux(Ajm1, Aj, Ajp1, c);  // flux at node t0-1

        #pragma unroll
        for (int k = 0; k < EPT; k++) {
            float dnext;
            switch (k) {
                case 0: dnext = q0.y; break;
                case 1: dnext = q0.z; break;
                case 2: dnext = q0.w; break;
                case 3: dnext = q1.x; break;
                case 4: dnext = q1.y; break;
                case 5: dnext = q1.z; break;
                case 6: dnext = q1.w; break;
                default: dnext = dp8; break;
            }
            // rotate window to center on node t0+k
            Ajm1 = Aj; Aj = Ajp1;
            {
                float inf;
                Ajp1 = ga_A(dnext, c, inf);
                if (k < EPT - 1) local_sum += inf;   // dp8 not owned
            }
            float fluxj  = face_flux(Ajm1, Aj, Ajp1, c);
            float A_next = fmaxf(fmaf(-c.dtdx, fluxj - flux_prev, Aj), 0.0f);
            float p      = manning_pc(A_next, c);
            float vel    = p * fminf(A_next * 1e8f, 1.0f);
            local_max    = fmaxf(local_max, vel);
            flux_prev    = fluxj;
        }
    } else {
        // ------------- guarded smem path (2 blocks) -------------
        #pragma unroll 1
        for (int k = tid; k < TILE + 8; k += BLOCK) {
            int g = base - 4 + k;
            float Aval = 0.0f;
            if (g >= 0 && g < N) {
                float infil;
                Aval = ga_A(depth[g], c, infil);
                if (g >= base && g < base + TILE)
                    local_sum += infil;
            }
            sA[k] = Aval;
        }
        __syncthreads();

        #pragma unroll 1
        for (int j = tid; j <= TILE; j += BLOCK) {
            int g   = base - 1 + j;
            float A = sA[j + 3];
            float slope = 0.0f;
            if (g > 0 && g < N - 1) {
                float d1 = A - sA[j + 2];
                float d2 = sA[j + 4] - A;
                float m  = (fabsf(d1) < fabsf(d2)) ? d1 : d2;
                slope    = (d1 * d2 > 0.0f) ? m : 0.0f;
            }
            float Aface = fmaf(0.5f, slope, A);
            sF[j] = Aface * manning_pc(Aface, c);
        }
        __syncthreads();

        #pragma unroll 1
        for (int k = tid; k < TILE; k += BLOCK) {
            int g = base + k;
            if (g < N) {
                float A       = sA[k + 4];
                float flux    = sF[k + 1];
                float flux_in = (g == 0) ? 0.0f : sF[k];
                float A_next  = fmaxf(fmaf(-c.dtdx, flux - flux_in, A), 0.0f);
                float p       = manning_pc(A_next, c);
                float vel     = p * fminf(A_next * 1e8f, 1.0f);
                local_max     = fmaxf(local_max, vel);
                if (g == N - 1)
                    g_outflow = A_next * p;
            }
        }
    }

    // ---- deterministic block reduction ----
    #pragma unroll
    for (int o = 16; o > 0; o >>= 1) {
        local_sum += __shfl_down_sync(0xffffffffu, local_sum, o);
        local_max  = fmaxf(local_max, __shfl_down_sync(0xffffffffu, local_max, o));
    }
    int warp = tid >> 5, lane = tid & 31;
    if (lane == 0) { wsum[warp] = local_sum; wmax[warp] = local_max; }
    __syncthreads();
    if (tid == 0) {
        float s = 0.0f, m = 0.0f;
        #pragma unroll
        for (int w = 0; w < BLOCK / 32; w++) {
            s += wsum[w];
            m = fmaxf(m, wmax[w]);
        }
        g_psum[blockIdx.x] = s;
        g_pmax[blockIdx.x] = m;
        __threadfence();
        unsigned int ticket = atomicAdd(&g_count, 1u);
        s_last = (ticket == (unsigned int)(nblocks - 1)) ? 1 : 0;
    }
    __syncthreads();

    // ---- last-to-finish block: fixed-order grid reduction + outputs ----
    if (s_last) {
        __threadfence();
        float s = 0.0f, m = 0.0f;
        for (int i = tid; i < nblocks; i += BLOCK) {
            s += g_psum[i];
            m  = fmaxf(m, g_pmax[i]);
        }
        #pragma unroll
        for (int o = 16; o > 0; o >>= 1) {
            s += __shfl_down_sync(0xffffffffu, s, o);
            m  = fmaxf(m, __shfl_down_sync(0xffffffffu, m, o));
        }
        if (lane == 0) { wsum[warp] = s; wmax[warp] = m; }
        __syncthreads();
        if (tid == 0) {
            float st = 0.0f, mt = 0.0f;
            #pragma unroll
            for (int w = 0; w < BLOCK / 32; w++) {
                st += wsum[w];
                mt  = fmaxf(mt, wmax[w]);
            }
            float mean_depth = st / (float)N;
            out[0] = g_outflow;
            out[1] = mean_depth * c.inv_dt;
            out[2] = mean_depth;
            out[3] = mt * c.dtdx;
            g_count = 0;   // reset for next graph replay
        }
    }
}

// ---------------------------------------------------------------------------
extern "C" void kernel_launch(void* const* d_in, const int* in_sizes, int n_in,
                              void* d_out, int out_size)
{
    const float* depth = (const float*)d_in[0];
    const int N = in_sizes[0];
    int nblocks = (N + TILE - 1) / TILE;
    if (nblocks > MAX_BLOCKS) nblocks = MAX_BLOCKS;  // N=2^22 -> 2048 blocks

    fused_kernel<<<nblocks, BLOCK>>>(
        depth, N, nblocks, (float*)d_out,
        (const float*)d_in[1],  (const float*)d_in[2],  (const float*)d_in[4],
        (const float*)d_in[5],  (const float*)d_in[6],  (const float*)d_in[7],
        (const float*)d_in[8],  (const float*)d_in[9],  (const float*)d_in[10],
        (const float*)d_in[11], (const float*)d_in[12], (const float*)d_in[13],
        (const float*)d_in[14]);
}

// round 5
// speedup vs baseline: 1.2301x; 1.2301x over previous
#include <cuda_runtime.h>
#include <math.h>

// ---------------------------------------------------------------------------
// PlaneElement fused, R5: smem-staged A + register rolling flux window.
// EPT=14 / TILE=3584 -> 1171 blocks = exactly one wave at 8 blocks/SM.
// __launch_bounds__(256,8) keeps regs <=32 for full occupancy.
// Output: [outflow_q, infil_rate_element, infil_depth_element, max_cfl]
// ---------------------------------------------------------------------------

#define BLOCK 256
#define EPT   14
#define TILE  (BLOCK * EPT)      // 3584
#define MAX_BLOCKS 8192
#define EPSF  1e-8f

struct Consts {
    float raindt;      // rain_rate * dt
    float Ka, Kb;      // fp*dt = Ka + Kb*depth
    float WID, rcpWID;
    float css;         // sqrt(1+SS1^2)+sqrt(1+SS2^2)
    float l2cman;      // log2(sqrt(SL)/MAN)
    float dtdx;        // dt/dx
    float inv_dt;
};

__device__ float        g_psum[MAX_BLOCKS];
__device__ float        g_pmax[MAX_BLOCKS];
__device__ float        g_outflow;
__device__ unsigned int g_count = 0;

__device__ __forceinline__ float fast_lg2(float x)
{ float r; asm("lg2.approx.f32 %0, %1;" : "=f"(r) : "f"(x)); return r; }
__device__ __forceinline__ float fast_ex2(float x)
{ float r; asm("ex2.approx.f32 %0, %1;" : "=f"(r) : "f"(x)); return r; }

// p' = (max(A,EPS)/wp)^(2/3) * cman   (cman folded into the exponent)
__device__ __forceinline__ float manning_pc(float A, const Consts& c)
{
    float h      = A * c.rcpWID;
    float wp     = fmaf(h, c.css, c.WID);
    float A_safe = fmaxf(A, EPSF);
    float r      = __fdividef(A_safe, wp);
    float e      = fmaf(0.66666667f, fast_lg2(r), c.l2cman);
    return fast_ex2(e);
}

__device__ __forceinline__ float ga_A(float d, const Consts& c, float& infil)
{
    float fpdt  = fmaf(c.Kb, d, c.Ka);
    float avail = c.raindt + d;
    infil       = fminf(fpdt, avail);
    return fmaxf(avail - infil, 0.0f) * c.WID;
}

// flux of node with window (Am, A0, Ap); no boundary guard (interior)
__device__ __forceinline__ float face_flux(float Am, float A0, float Ap, const Consts& c)
{
    float a = A0 - Am;
    float b = Ap - A0;
    float m = (fabsf(a) < fabsf(b)) ? a : b;
    float s = (a * b > 0.0f) ? m : 0.0f;
    float Af = fmaf(0.5f, s, A0);
    return Af * manning_pc(Af, c);
}

__global__ void __launch_bounds__(BLOCK, 8)
fused_kernel(const float* __restrict__ depth, int N, int nblocks,
             float* __restrict__ out,
             const float* rain_rate, const float* dt,
             const float* theta_current, const float* F_cumulative,
             const float* WID, const float* SS1, const float* SS2,
             const float* MAN, const float* SL, const float* dx,
             const float* Ks, const float* psi, const float* theta_s)
{
    // sAraw[k] = A at global index (base - 4 + k). Owned g at k = g-base+4
    // (16B-aligned float4 stores), halo base-2,-1 at k=2,3; base+TILE at TILE+4.
    __shared__ __align__(16) float sAraw[TILE + 8];
    __shared__ Consts sc;
    __shared__ float wsum[BLOCK / 32];
    __shared__ float wmax[BLOCK / 32];
    __shared__ int   s_last;

    const int tid  = threadIdx.x;
    const int base = blockIdx.x * TILE;

    if (tid == 0) {
        float rr  = *rain_rate,  dtv = *dt,  th = *theta_current, F = *F_cumulative;
        float wid = *WID, ss1 = *SS1, ss2 = *SS2, man = *MAN, sl = *SL, dxv = *dx;
        float ks  = *Ks,  ps  = *psi, ths = *theta_s;
        Consts c;
        c.raindt = rr * dtv;
        float dtheta = fmaxf(ths - th, 0.0f);
        float F_safe = fmaxf(F, 1e-6f);
        float ksdt   = ks * dtv;
        c.Kb = ksdt / F_safe;
        c.Ka = ksdt + c.Kb * (ps * dtheta);
        c.WID = wid;
        c.rcpWID = 1.0f / wid;
        c.css  = sqrtf(1.0f + ss1 * ss1) + sqrtf(1.0f + ss2 * ss2);
        c.l2cman = log2f(sqrtf(sl) / man);
        c.dtdx = dtv / dxv;
        c.inv_dt = 1.0f / dtv;
        sc = c;
    }
    __syncthreads();
    const Consts c = sc;

    // interior: halo in range AND no global-boundary slope guards needed
    const bool interior = (base >= 2) && (base + TILE + 2 <= N);

    float local_sum = 0.0f;
    float local_max = 0.0f;

    if (interior) {
        // ---- stage A into smem (coalesced float4 Green-Ampt) ----
        const float4* dp = (const float4*)(depth + base);
        float4* sA4 = (float4*)(sAraw + 4);
        #pragma unroll 1
        for (int idx = tid; idx < TILE / 4; idx += BLOCK) {
            float4 d4 = __ldg(dp + idx);
            float i0, i1, i2, i3;
            float4 a4;
            a4.x = ga_A(d4.x, c, i0);
            a4.y = ga_A(d4.y, c, i1);
            a4.z = ga_A(d4.z, c, i2);
            a4.w = ga_A(d4.w, c, i3);
            local_sum += (i0 + i1) + (i2 + i3);
            sA4[idx] = a4;
        }
        if (tid < 3) {
            int g = (tid < 2) ? (base - 2 + tid) : (base + TILE);
            float junk;
            sAraw[g - base + 4] = ga_A(__ldg(depth + g), c, junk);
        }
        __syncthreads();

        // ---- rolling window: 15 face fluxes + 14 updates, flux in regs ----
        const int s0 = tid * EPT + 2;       // sAraw[s0] = A(t0-2)
        float Am = sAraw[s0];
        float A0 = sAraw[s0 + 1];
        float Ap = sAraw[s0 + 2];
        float flux_prev = face_flux(Am, A0, Ap, c);   // node t0-1
        #pragma unroll
        for (int i = 0; i < EPT; i++) {
            Am = A0; A0 = Ap; Ap = sAraw[s0 + 3 + i];
            float fluxj  = face_flux(Am, A0, Ap, c);
            float A_next = fmaxf(fmaf(-c.dtdx, fluxj - flux_prev, A0), 0.0f);
            float p      = manning_pc(A_next, c);
            local_max    = fmaxf(local_max, p * fminf(A_next * 1e8f, 1.0f));
            flux_prev    = fluxj;
        }
    } else {
        // ---- edge blocks (2): guarded staging + guarded window ----
        #pragma unroll 1
        for (int k = tid; k < TILE + 3; k += BLOCK) {
            int g = base - 2 + k;
            float Aval = 0.0f;
            if (g >= 0 && g < N) {
                float infil;
                Aval = ga_A(depth[g], c, infil);
                if (g >= base) local_sum += infil;   // owned (g < base+TILE by range)
            }
            sAraw[k + 2] = Aval;
        }
        __syncthreads();

        const int t0 = base + tid * EPT;
        float flux_prev = 0.0f;
        {   // flux at node t0-1 (if it exists)
            int j = t0 - 1;
            if (j >= 0 && j < N) {
                int sj = j - base + 4;
                float A = sAraw[sj];
                float slope = 0.0f;
                if (j > 0 && j < N - 1) {
                    float a = A - sAraw[sj - 1];
                    float b = sAraw[sj + 1] - A;
                    float m = (fabsf(a) < fabsf(b)) ? a : b;
                    slope   = (a * b > 0.0f) ? m : 0.0f;
                }
                float Af = fmaf(0.5f, slope, A);
                flux_prev = Af * manning_pc(Af, c);
            }
        }
        #pragma unroll 1
        for (int i = 0; i < EPT; i++) {
            int g = t0 + i;
            if (g >= N) break;
            int sg = g - base + 4;
            float A = sAraw[sg];
            float slope = 0.0f;
            if (g > 0 && g < N - 1) {
                float a = A - sAraw[sg - 1];
                float b = sAraw[sg + 1] - A;
                float m = (fabsf(a) < fabsf(b)) ? a : b;
                slope   = (a * b > 0.0f) ? m : 0.0f;
            }
            float Af    = fmaf(0.5f, slope, A);
            float fluxj = Af * manning_pc(Af, c);
            float flux_in = (g == 0) ? 0.0f : flux_prev;
            float A_next  = fmaxf(fmaf(-c.dtdx, fluxj - flux_in, A), 0.0f);
            float p       = manning_pc(A_next, c);
            local_max     = fmaxf(local_max, p * fminf(A_next * 1e8f, 1.0f));
            if (g == N - 1) g_outflow = A_next * p;
            flux_prev = fluxj;
        }
    }

    // ---- deterministic block reduction ----
    #pragma unroll
    for (int o = 16; o > 0; o >>= 1) {
        local_sum += __shfl_down_sync(0xffffffffu, local_sum, o);
        local_max  = fmaxf(local_max, __shfl_down_sync(0xffffffffu, local_max, o));
    }
    int warp = tid >> 5, lane = tid & 31;
    if (lane == 0) { wsum[warp] = local_sum; wmax[warp] = local_max; }
    __syncthreads();
    if (tid == 0) {
        float s = 0.0f, m = 0.0f;
        #pragma unroll
        for (int w = 0; w < BLOCK / 32; w++) {
            s += wsum[w];
            m = fmaxf(m, wmax[w]);
        }
        g_psum[blockIdx.x] = s;
        g_pmax[blockIdx.x] = m;
        __threadfence();
        unsigned int ticket = atomicAdd(&g_count, 1u);
        s_last = (ticket == (unsigned int)(nblocks - 1)) ? 1 : 0;
    }
    __syncthreads();

    // ---- last-to-finish block: fixed-order grid reduction + outputs ----
    if (s_last) {
        __threadfence();
        float s = 0.0f, m = 0.0f;
        for (int i = tid; i < nblocks; i += BLOCK) {
            s += g_psum[i];
            m  = fmaxf(m, g_pmax[i]);
        }
        #pragma unroll
        for (int o = 16; o > 0; o >>= 1) {
            s += __shfl_down_sync(0xffffffffu, s, o);
            m  = fmaxf(m, __shfl_down_sync(0xffffffffu, m, o));
        }
        if (lane == 0) { wsum[warp] = s; wmax[warp] = m; }
        __syncthreads();
        if (tid == 0) {
            float st = 0.0f, mt = 0.0f;
            #pragma unroll
            for (int w = 0; w < BLOCK / 32; w++) {
                st += wsum[w];
                mt  = fmaxf(mt, wmax[w]);
            }
            float mean_depth = st / (float)N;
            out[0] = g_outflow;
            out[1] = mean_depth * c.inv_dt;
            out[2] = mean_depth;
            out[3] = mt * c.dtdx;
            g_count = 0;   // reset for next graph replay
        }
    }
}

// ---------------------------------------------------------------------------
extern "C" void kernel_launch(void* const* d_in, const int* in_sizes, int n_in,
                              void* d_out, int out_size)
{
    const float* depth = (const float*)d_in[0];
    const int N = in_sizes[0];
    int nblocks = (N + TILE - 1) / TILE;   // N=2^22 -> 1171 blocks (single wave)
    if (nblocks > MAX_BLOCKS) nblocks = MAX_BLOCKS;

    fused_kernel<<<nblocks, BLOCK>>>(
        depth, N, nblocks, (float*)d_out,
        (const float*)d_in[1],  (const float*)d_in[2],  (const float*)d_in[4],
        (const float*)d_in[5],  (const float*)d_in[6],  (const float*)d_in[7],
        (const float*)d_in[8],  (const float*)d_in[9],  (const float*)d_in[10],
        (const float*)d_in[11], (const float*)d_in[12], (const float*)d_in[13],
        (const float*)d_in[14]);
}